// round 1
// baseline (speedup 1.0000x reference)
#include <cuda_runtime.h>
#include <cuda_bf16.h>
#include <cstdint>

// Problem dims
#define B_NO   8
#define T_DATA 5000
#define E_NO   2000
#define SUB_NO 20
#define HID_NO 10
#define SH_NO  (SUB_NO * HID_NO)   // 200
#define T_NO   50
#define NCH    (B_NO * SH_NO)      // 1600 channels

// Scratch (device globals — no allocation at runtime)
__device__ float g_CT[E_NO * SUB_NO];                 // [e][s] scaled C
__device__ float g_syn[B_NO * SUB_NO * T_DATA];       // [b][s][t]
__device__ float g_conv[B_NO * SH_NO * (size_t)T_DATA]; // [b][c][t]
__device__ float g_ybuf[B_NO * SH_NO * (size_t)T_DATA]; // [b][c][t]  ew2*y

// ---------- f32x2 helpers ----------
__device__ __forceinline__ unsigned long long pk2(float x, float y) {
    unsigned long long r;
    asm("mov.b64 %0, {%1, %2};" : "=l"(r) : "f"(x), "f"(y));
    return r;
}
__device__ __forceinline__ unsigned long long ffma2(unsigned long long a,
                                                    unsigned long long b,
                                                    unsigned long long c) {
    unsigned long long d;
    asm("fma.rn.f32x2 %0, %1, %2, %3;" : "=l"(d) : "l"(a), "l"(b), "l"(c));
    return d;
}
__device__ __forceinline__ float2 upk2(unsigned long long v) {
    float2 f;
    asm("mov.b64 {%0, %1}, %2;" : "=f"(f.x), "=f"(f.y) : "l"(v));
    return f;
}

__device__ __forceinline__ float tanh_fast(float x) {
    // tanh(x) = 1 - 2/(e^{2x}+1); exact limits at +-inf; ~1e-6 rel err
    float e = __expf(2.0f * x);
    return 1.0f - __fdividef(2.0f, e + 1.0f);
}

// ---------- 1. prep: CT[e][s] = C[s][e] * exp(E_scale[e]) ----------
__global__ void prep_kernel(const float* __restrict__ C, const float* __restrict__ Esc) {
    int i = blockIdx.x * 256 + threadIdx.x;
    if (i >= E_NO * SUB_NO) return;
    int e = i / SUB_NO, s = i % SUB_NO;
    g_CT[i] = C[s * E_NO + e] * expf(Esc[e]);
}

// ---------- 2. GEMM: syn[b][s][t] = sum_e S_e[b][t][e] * CT[e][s] ----------
// block: 128 threads, each computes 2 rows (t, t+128) x 20 outputs, via f32x2
__global__ void __launch_bounds__(128) gemm_kernel(const float* __restrict__ S_e) {
    __shared__ float sS[256 * 33];      // 256 rows x 32 e, padded
    __shared__ float sC[32 * 20];       // [e_loc][s]
    const int b = blockIdx.y;
    const int t0 = blockIdx.x * 256;
    const int tid = threadIdx.x;

    unsigned long long acc0[10], acc1[10];
#pragma unroll
    for (int s = 0; s < 10; s++) { acc0[s] = 0ull; acc1[s] = 0ull; }

    const float* Sb = S_e + (size_t)b * T_DATA * E_NO;

    for (int e0 = 0; e0 < E_NO; e0 += 32) {
#pragma unroll
        for (int k = 0; k < 5; k++) {
            int i = tid + k * 128;
            sC[i] = g_CT[(e0 + i / 20) * 20 + (i % 20)];
        }
#pragma unroll 8
        for (int k = 0; k < 64; k++) {
            int l = tid + k * 128;
            int r = l >> 5, j = l & 31;
            int t = t0 + r;
            sS[r * 33 + j] = (t < T_DATA) ? Sb[(size_t)t * E_NO + e0 + j] : 0.0f;
        }
        __syncthreads();
#pragma unroll 8
        for (int j = 0; j < 32; j++) {
            unsigned long long cp[10];
#pragma unroll
            for (int s = 0; s < 10; s++)
                cp[s] = *(const unsigned long long*)&sC[j * 20 + 2 * s];
            float v0 = sS[tid * 33 + j];
            float v1 = sS[(tid + 128) * 33 + j];
            unsigned long long v0p = pk2(v0, v0), v1p = pk2(v1, v1);
#pragma unroll
            for (int s = 0; s < 10; s++) {
                acc0[s] = ffma2(v0p, cp[s], acc0[s]);
                acc1[s] = ffma2(v1p, cp[s], acc1[s]);
            }
        }
        __syncthreads();
    }

    int ta = t0 + tid;
    if (ta < T_DATA) {
#pragma unroll
        for (int s = 0; s < 10; s++) {
            float2 f = upk2(acc0[s]);
            g_syn[((size_t)b * SUB_NO + 2 * s)     * T_DATA + ta] = f.x;
            g_syn[((size_t)b * SUB_NO + 2 * s + 1) * T_DATA + ta] = f.y;
        }
    }
    int tb = t0 + 128 + tid;
    if (tb < T_DATA) {
#pragma unroll
        for (int s = 0; s < 10; s++) {
            float2 f = upk2(acc1[s]);
            g_syn[((size_t)b * SUB_NO + 2 * s)     * T_DATA + tb] = f.x;
            g_syn[((size_t)b * SUB_NO + 2 * s + 1) * T_DATA + tb] = f.y;
        }
    }
}

// ---------- 3. depthwise causal conv ----------
// conv[b][c][t] = sum_{tau=0..49} syn[b][c/10][t-tau] * W1[c][tau]
__global__ void __launch_bounds__(256) conv_kernel(const float* __restrict__ W1) {
    const int bs = blockIdx.x;            // 0..159
    const int b = bs / SUB_NO, s = bs % SUB_NO;
    __shared__ float ss[T_NO - 1 + T_DATA];   // 49 zeros + 5000
    const int tid = threadIdx.x;

    for (int i = tid; i < T_NO - 1; i += 256) ss[i] = 0.0f;
    const float* sp = g_syn + ((size_t)b * SUB_NO + s) * T_DATA;
    for (int i = tid; i < T_DATA; i += 256) ss[T_NO - 1 + i] = sp[i];
    __syncthreads();

    for (int h = 0; h < HID_NO; h++) {
        const int c = s * HID_NO + h;
        float w[T_NO];
#pragma unroll
        for (int i = 0; i < T_NO; i++) w[i] = __ldg(&W1[c * T_NO + i]);
        float* cp = g_conv + ((size_t)(b * SH_NO + c)) * T_DATA;
        for (int t = tid; t < T_DATA; t += 256) {
            float acc = 0.0f;
#pragma unroll
            for (int tau = 0; tau < T_NO; tau++)
                acc = fmaf(ss[T_NO - 1 + t - tau], w[tau], acc);
            cp[t] = acc;
        }
    }
}

// ---------- 4. recurrence (scatter form, register window) ----------
// y[t] = tanh( sum_{tau=1..50} y[t-tau]*Wh[c][tau-1] + conv[b][c][t] + bias )
__global__ void __launch_bounds__(32, 1) recur_kernel(const float* __restrict__ Wh,
                                                      const float* __restrict__ b1,
                                                      const float* __restrict__ W2) {
    const int cid = blockIdx.x * 32 + threadIdx.x;
    if (cid >= NCH) return;
    const int c = cid % SH_NO;

    const float* cv = g_conv + (size_t)cid * T_DATA;
    float* yo = g_ybuf + (size_t)cid * T_DATA;

    float w[T_NO];
#pragma unroll
    for (int i = 0; i < T_NO; i++) w[i] = __ldg(&Wh[c * T_NO + i]);
    const float bias = b1[c];
    const float ew2 = expf(W2[c]);

    float acc[100];
#pragma unroll
    for (int j = 0; j < 100; j++) acc[j] = bias;

    for (int t0 = 0; t0 < T_DATA; t0 += 50) {
        // add conv for the 50 upcoming steps
#pragma unroll
        for (int j = 0; j < 50; j += 2) {
            float2 cc = *(const float2*)(cv + t0 + j);
            acc[j]     += cc.x;
            acc[j + 1] += cc.y;
        }
#pragma unroll
        for (int p = 0; p < 50; p++) {
            float y = tanh_fast(acc[p]);
            yo[t0 + p] = ew2 * y;
#pragma unroll
            for (int tau = 1; tau <= 50; tau++)
                acc[p + tau] = fmaf(y, w[tau - 1], acc[p + tau]);
        }
#pragma unroll
        for (int j = 0; j < 50; j++) { acc[j] = acc[j + 50]; acc[j + 50] = bias; }
    }
}

// ---------- 5. reduce: out[b][t] = V_o + sum_c ybuf[b][c][t] ----------
__global__ void __launch_bounds__(256) reduce_kernel(const float* __restrict__ V_o,
                                                     float* __restrict__ out) {
    int idx = blockIdx.x * 256 + threadIdx.x;
    if (idx >= B_NO * T_DATA) return;
    int b = idx / T_DATA, t = idx % T_DATA;
    const float* p = g_ybuf + (size_t)b * SH_NO * T_DATA + t;
    float a = V_o[0];
#pragma unroll 10
    for (int c = 0; c < SH_NO; c++) a += p[(size_t)c * T_DATA];
    out[idx] = a;
}

extern "C" void kernel_launch(void* const* d_in, const int* in_sizes, int n_in,
                              void* d_out, int out_size) {
    const float* S_e     = (const float*)d_in[0];
    // d_in[1] S_i, d_in[3] C_syn_i, d_in[5] I_scale, d_in[10] W_sub: unused
    const float* C_syn_e = (const float*)d_in[2];
    const float* E_scale = (const float*)d_in[4];
    const float* W1      = (const float*)d_in[6];
    const float* W2      = (const float*)d_in[7];
    const float* b1      = (const float*)d_in[8];
    const float* Wh      = (const float*)d_in[9];
    const float* V_o     = (const float*)d_in[11];
    float* out = (float*)d_out;

    prep_kernel<<<(E_NO * SUB_NO + 255) / 256, 256>>>(C_syn_e, E_scale);
    dim3 gg((T_DATA + 255) / 256, B_NO);
    gemm_kernel<<<gg, 128>>>(S_e);
    conv_kernel<<<B_NO * SUB_NO, 256>>>(W1);
    recur_kernel<<<(NCH + 31) / 32, 32>>>(Wh, b1, W2);
    reduce_kernel<<<(B_NO * T_DATA + 255) / 256, 256>>>(V_o, out);
}

// round 2
// speedup vs baseline: 1.1735x; 1.1735x over previous
#include <cuda_runtime.h>
#include <cuda_bf16.h>
#include <cstdint>

// Problem dims
#define B_NO   8
#define T_DATA 5000
#define E_NO   2000
#define SUB_NO 20
#define HID_NO 10
#define SH_NO  (SUB_NO * HID_NO)   // 200
#define T_NO   50
#define NCH    (B_NO * SH_NO)      // 1600 channels

// Recurrence pipeline config
#define P_CHUNK 10
#define NCHUNKS (T_DATA / P_CHUNK)  // 500
#define TA 22                       // critical-warp taps 1..22
#define TB 28                       // helper-warp taps 23..50
#define YH 40                       // helper y-history depth

// Scratch (device globals — no allocation at runtime)
__device__ float g_CT[E_NO * SUB_NO];                   // [e][s] scaled C
__device__ float g_syn[B_NO * SUB_NO * T_DATA];         // [b][s][t]
__device__ float g_conv[B_NO * SH_NO * (size_t)T_DATA]; // [b][c][t]
__device__ float g_ybuf[B_NO * SH_NO * (size_t)T_DATA]; // [b][c][t]  ew2*y

// ---------- f32x2 helpers ----------
__device__ __forceinline__ unsigned long long pk2(float x, float y) {
    unsigned long long r;
    asm("mov.b64 %0, {%1, %2};" : "=l"(r) : "f"(x), "f"(y));
    return r;
}
__device__ __forceinline__ unsigned long long ffma2(unsigned long long a,
                                                    unsigned long long b,
                                                    unsigned long long c) {
    unsigned long long d;
    asm("fma.rn.f32x2 %0, %1, %2, %3;" : "=l"(d) : "l"(a), "l"(b), "l"(c));
    return d;
}
__device__ __forceinline__ float2 upk2(unsigned long long v) {
    float2 f;
    asm("mov.b64 {%0, %1}, %2;" : "=f"(f.x), "=f"(f.y) : "l"(v));
    return f;
}

__device__ __forceinline__ float tanh_fast(float x) {
    // tanh(x) = 1 - 2/(e^{2x}+1); exact limits at +-inf; ~1e-6 rel err
    float e = __expf(2.0f * x);
    return 1.0f - __fdividef(2.0f, e + 1.0f);
}

// ---------- 1. prep: CT[e][s] = C[s][e] * exp(E_scale[e]) ----------
__global__ void prep_kernel(const float* __restrict__ C, const float* __restrict__ Esc) {
    int i = blockIdx.x * 256 + threadIdx.x;
    if (i >= E_NO * SUB_NO) return;
    int e = i / SUB_NO, s = i % SUB_NO;
    g_CT[i] = C[s * E_NO + e] * expf(Esc[e]);
}

// ---------- 2. GEMM: syn[b][s][t] = sum_e S_e[b][t][e] * CT[e][s] ----------
__global__ void __launch_bounds__(128) gemm_kernel(const float* __restrict__ S_e) {
    __shared__ float sS[256 * 33];      // 256 rows x 32 e, padded
    __shared__ float sC[32 * 20];       // [e_loc][s]
    const int b = blockIdx.y;
    const int t0 = blockIdx.x * 256;
    const int tid = threadIdx.x;

    unsigned long long acc0[10], acc1[10];
#pragma unroll
    for (int s = 0; s < 10; s++) { acc0[s] = 0ull; acc1[s] = 0ull; }

    const float* Sb = S_e + (size_t)b * T_DATA * E_NO;

    for (int e0 = 0; e0 < E_NO; e0 += 32) {
#pragma unroll
        for (int k = 0; k < 5; k++) {
            int i = tid + k * 128;
            sC[i] = g_CT[(e0 + i / 20) * 20 + (i % 20)];
        }
#pragma unroll 8
        for (int k = 0; k < 64; k++) {
            int l = tid + k * 128;
            int r = l >> 5, j = l & 31;
            int t = t0 + r;
            sS[r * 33 + j] = (t < T_DATA) ? Sb[(size_t)t * E_NO + e0 + j] : 0.0f;
        }
        __syncthreads();
#pragma unroll 8
        for (int j = 0; j < 32; j++) {
            unsigned long long cp[10];
#pragma unroll
            for (int s = 0; s < 10; s++)
                cp[s] = *(const unsigned long long*)&sC[j * 20 + 2 * s];
            float v0 = sS[tid * 33 + j];
            float v1 = sS[(tid + 128) * 33 + j];
            unsigned long long v0p = pk2(v0, v0), v1p = pk2(v1, v1);
#pragma unroll
            for (int s = 0; s < 10; s++) {
                acc0[s] = ffma2(v0p, cp[s], acc0[s]);
                acc1[s] = ffma2(v1p, cp[s], acc1[s]);
            }
        }
        __syncthreads();
    }

    int ta = t0 + tid;
    if (ta < T_DATA) {
#pragma unroll
        for (int s = 0; s < 10; s++) {
            float2 f = upk2(acc0[s]);
            g_syn[((size_t)b * SUB_NO + 2 * s)     * T_DATA + ta] = f.x;
            g_syn[((size_t)b * SUB_NO + 2 * s + 1) * T_DATA + ta] = f.y;
        }
    }
    int tb = t0 + 128 + tid;
    if (tb < T_DATA) {
#pragma unroll
        for (int s = 0; s < 10; s++) {
            float2 f = upk2(acc1[s]);
            g_syn[((size_t)b * SUB_NO + 2 * s)     * T_DATA + tb] = f.x;
            g_syn[((size_t)b * SUB_NO + 2 * s + 1) * T_DATA + tb] = f.y;
        }
    }
}

// ---------- 3. depthwise causal conv ----------
__global__ void __launch_bounds__(256) conv_kernel(const float* __restrict__ W1) {
    const int bs = blockIdx.x;            // 0..159
    const int b = bs / SUB_NO, s = bs % SUB_NO;
    __shared__ float ss[T_NO - 1 + T_DATA];   // 49 zeros + 5000
    const int tid = threadIdx.x;

    for (int i = tid; i < T_NO - 1; i += 256) ss[i] = 0.0f;
    const float* sp = g_syn + ((size_t)b * SUB_NO + s) * T_DATA;
    for (int i = tid; i < T_DATA; i += 256) ss[T_NO - 1 + i] = sp[i];
    __syncthreads();

    for (int h = 0; h < HID_NO; h++) {
        const int c = s * HID_NO + h;
        float w[T_NO];
#pragma unroll
        for (int i = 0; i < T_NO; i++) w[i] = __ldg(&W1[c * T_NO + i]);
        float* cp = g_conv + ((size_t)(b * SH_NO + c)) * T_DATA;
        for (int t = tid; t < T_DATA; t += 256) {
            float acc = 0.0f;
#pragma unroll
            for (int tau = 0; tau < T_NO; tau++)
                acc = fmaf(ss[T_NO - 1 + t - tau], w[tau], acc);
            cp[t] = acc;
        }
    }
}

// ---------- 4. recurrence: warp-specialized producer/consumer pipeline ----------
// y[t] = tanh( sum_{tau=1..50} y[t-tau]*Wh[c][tau-1] + conv[b][c][t] + b1[c] )
// Warp 0 (A): serial chain with taps 1..TA, scatter window acc[P+TA].
// Warp 1 (B): gathers lagged taps TA+1..50 for the NEXT chunk + conv + bias,
//             handles all GMEM I/O; overlaps with A's serial phase.
__global__ void __launch_bounds__(64, 1) recur_kernel(const float* __restrict__ Wh,
                                                      const float* __restrict__ b1,
                                                      const float* __restrict__ W2) {
    __shared__ float s_y[2][32][P_CHUNK + 1];     // pad to 11 floats: conflict-free
    __shared__ float s_part[2][32][P_CHUNK + 1];

    const int lane = threadIdx.x & 31;
    const int warp = threadIdx.x >> 5;
    const int ch = blockIdx.x * 32 + lane;        // 0..1599
    const int c = ch % SH_NO;

    if (warp == 0) {
        // ---------------- Warp A: critical serial chain ----------------
        float w[TA];
#pragma unroll
        for (int i = 0; i < TA; i++) w[i] = __ldg(&Wh[c * T_NO + i]);  // tau = i+1

        float acc[P_CHUNK + TA];                  // 32 slots
#pragma unroll
        for (int j = 0; j < P_CHUNK + TA; j++) acc[j] = 0.0f;

        __syncthreads();                          // matches B prologue sync

        for (int k = 0; k < NCHUNKS; k++) {
            const float* part = &s_part[k & 1][lane][0];
            float* yrow = &s_y[k & 1][lane][0];
#pragma unroll
            for (int p = 0; p < P_CHUNK; p++) {
                float v = acc[p] + part[p];
                float y = tanh_fast(v);
                yrow[p] = y;
#pragma unroll
                for (int tau = 1; tau <= TA; tau++)
                    acc[p + tau] = fmaf(y, w[tau - 1], acc[p + tau]);
            }
            // shift window by P_CHUNK
#pragma unroll
            for (int j = 0; j < TA; j++) acc[j] = acc[j + P_CHUNK];
#pragma unroll
            for (int j = TA; j < P_CHUNK + TA; j++) acc[j] = 0.0f;
            __syncthreads();
        }
    } else {
        // ---------------- Warp B: lagged gather + all I/O ----------------
        float wB[TB];
#pragma unroll
        for (int u = 0; u < TB; u++) wB[u] = __ldg(&Wh[c * T_NO + TA + u]); // tau = TA+1+u

        const float bias = b1[c];
        const float ew2 = expf(W2[c]);
        const float* cv = g_conv + (size_t)ch * T_DATA;
        float* yo = g_ybuf + (size_t)ch * T_DATA;

        float yh[YH];                             // yh[i] = y[P*k - YH + i] at iter k
#pragma unroll
        for (int i = 0; i < YH; i++) yh[i] = 0.0f;

        // prologue: partials for chunk 0 (no y history yet)
        {
            float2 cc[P_CHUNK / 2];
#pragma unroll
            for (int q = 0; q < P_CHUNK / 2; q++) cc[q] = *(const float2*)(cv + 2 * q);
#pragma unroll
            for (int q = 0; q < P_CHUNK / 2; q++) {
                s_part[0][lane][2 * q]     = cc[q].x + bias;
                s_part[0][lane][2 * q + 1] = cc[q].y + bias;
            }
        }
        __syncthreads();

        for (int k = 0; k < NCHUNKS; k++) {
            if (k > 0) {
                // pull chunk k-1 ys, emit outputs, update history
                float yn[P_CHUNK];
#pragma unroll
                for (int j = 0; j < P_CHUNK; j++) yn[j] = s_y[(k - 1) & 1][lane][j];
                const int tb = P_CHUNK * (k - 1);
#pragma unroll
                for (int q = 0; q < P_CHUNK / 2; q++) {
                    float2 o = make_float2(ew2 * yn[2 * q], ew2 * yn[2 * q + 1]);
                    *(float2*)(yo + tb + 2 * q) = o;
                }
#pragma unroll
                for (int i = 0; i < YH - P_CHUNK; i++) yh[i] = yh[i + P_CHUNK];
#pragma unroll
                for (int j = 0; j < P_CHUNK; j++) yh[YH - P_CHUNK + j] = yn[j];
            }
            if (k + 1 < NCHUNKS) {
                const int t1 = P_CHUNK * (k + 1);
                float part[P_CHUNK];
                float2 cc[P_CHUNK / 2];
#pragma unroll
                for (int q = 0; q < P_CHUNK / 2; q++)
                    cc[q] = *(const float2*)(cv + t1 + 2 * q);
#pragma unroll
                for (int q = 0; q < P_CHUNK / 2; q++) {
                    part[2 * q]     = cc[q].x + bias;
                    part[2 * q + 1] = cc[q].y + bias;
                }
                // gather taps TA+1..50: y index time = t1+j-tau,
                // yh idx = 50+j-tau = (T_NO - TA - 1) + j - u  with tau = TA+1+u
#pragma unroll
                for (int j = 0; j < P_CHUNK; j++) {
#pragma unroll
                    for (int u = 0; u < TB; u++)
                        part[j] = fmaf(yh[(T_NO - TA - 1) + j - u], wB[u], part[j]);
                }
#pragma unroll
                for (int j = 0; j < P_CHUNK; j++)
                    s_part[(k + 1) & 1][lane][j] = part[j];
            }
            __syncthreads();
        }
        // epilogue: final chunk's outputs
        {
            const int tb = T_DATA - P_CHUNK;
#pragma unroll
            for (int j = 0; j < P_CHUNK; j++) {
                float y = s_y[(NCHUNKS - 1) & 1][lane][j];
                yo[tb + j] = ew2 * y;
            }
        }
    }
}

// ---------- 5. reduce: out[b][t] = V_o + sum_c ybuf[b][c][t] ----------
__global__ void __launch_bounds__(256) reduce_kernel(const float* __restrict__ V_o,
                                                     float* __restrict__ out) {
    int idx = blockIdx.x * 256 + threadIdx.x;
    if (idx >= B_NO * T_DATA) return;
    int b = idx / T_DATA, t = idx % T_DATA;
    const float* p = g_ybuf + (size_t)b * SH_NO * T_DATA + t;
    float a = V_o[0];
#pragma unroll 10
    for (int c = 0; c < SH_NO; c++) a += p[(size_t)c * T_DATA];
    out[idx] = a;
}

extern "C" void kernel_launch(void* const* d_in, const int* in_sizes, int n_in,
                              void* d_out, int out_size) {
    const float* S_e     = (const float*)d_in[0];
    // d_in[1] S_i, d_in[3] C_syn_i, d_in[5] I_scale, d_in[10] W_sub: unused
    const float* C_syn_e = (const float*)d_in[2];
    const float* E_scale = (const float*)d_in[4];
    const float* W1      = (const float*)d_in[6];
    const float* W2      = (const float*)d_in[7];
    const float* b1      = (const float*)d_in[8];
    const float* Wh      = (const float*)d_in[9];
    const float* V_o     = (const float*)d_in[11];
    float* out = (float*)d_out;

    prep_kernel<<<(E_NO * SUB_NO + 255) / 256, 256>>>(C_syn_e, E_scale);
    dim3 gg((T_DATA + 255) / 256, B_NO);
    gemm_kernel<<<gg, 128>>>(S_e);
    conv_kernel<<<B_NO * SUB_NO, 256>>>(W1);
    recur_kernel<<<(NCH + 31) / 32, 64>>>(Wh, b1, W2);
    reduce_kernel<<<(B_NO * T_DATA + 255) / 256, 256>>>(V_o, out);
}

// round 3
// speedup vs baseline: 1.3194x; 1.1244x over previous
#include <cuda_runtime.h>
#include <cuda_bf16.h>
#include <cstdint>

// Problem dims
#define B_NO   8
#define T_DATA 5000
#define E_NO   2000
#define SUB_NO 20
#define HID_NO 10
#define SH_NO  (SUB_NO * HID_NO)   // 200
#define T_NO   50
#define NCH    (B_NO * SH_NO)      // 1600 channels

// Recurrence pipeline config
#define PCH 10
#define NCHUNKS (T_DATA / PCH)     // 500
#define TA  20                     // warp A taps 1..20 (minimum for PCH=10)
#define TBH 15                     // taps per helper warp (21..35 and 36..50)

// Scratch (device globals — no allocation at runtime)
__device__ float g_CT[E_NO * SUB_NO];                   // [e][s] scaled C
__device__ float g_syn[B_NO * SUB_NO * T_DATA];         // [b][s][t]
__device__ float g_conv[B_NO * SH_NO * (size_t)T_DATA]; // [b][c][t]
__device__ float g_ybuf[B_NO * SH_NO * (size_t)T_DATA]; // [b][c][t]  ew2*y

// ---------- f32x2 helpers ----------
__device__ __forceinline__ unsigned long long pk2(float x, float y) {
    unsigned long long r;
    asm("mov.b64 %0, {%1, %2};" : "=l"(r) : "f"(x), "f"(y));
    return r;
}
__device__ __forceinline__ unsigned long long ffma2(unsigned long long a,
                                                    unsigned long long b,
                                                    unsigned long long c) {
    unsigned long long d;
    asm("fma.rn.f32x2 %0, %1, %2, %3;" : "=l"(d) : "l"(a), "l"(b), "l"(c));
    return d;
}
__device__ __forceinline__ unsigned long long add2(unsigned long long a,
                                                   unsigned long long b) {
    unsigned long long d;
    asm("add.rn.f32x2 %0, %1, %2;" : "=l"(d) : "l"(a), "l"(b));
    return d;
}
__device__ __forceinline__ float2 upk2(unsigned long long v) {
    float2 f;
    asm("mov.b64 {%0, %1}, %2;" : "=f"(f.x), "=f"(f.y) : "l"(v));
    return f;
}

__device__ __forceinline__ float tanh_fast(float x) {
    // tanh(x) = 1 - 2/(e^{2x}+1); inf-safe; chain: FMUL+EX2+FADD+RCP+FFMA
    float z = x * 2.8853900817779268f;   // 2*log2(e)
    float e;
    asm("ex2.approx.f32 %0, %1;" : "=f"(e) : "f"(z));
    float r;
    asm("rcp.approx.f32 %0, %1;" : "=f"(r) : "f"(e + 1.0f));
    return fmaf(-2.0f, r, 1.0f);
}

// ---------- 1. prep: CT[e][s] = C[s][e] * exp(E_scale[e]) ----------
__global__ void prep_kernel(const float* __restrict__ C, const float* __restrict__ Esc) {
    int i = blockIdx.x * 256 + threadIdx.x;
    if (i >= E_NO * SUB_NO) return;
    int e = i / SUB_NO, s = i % SUB_NO;
    g_CT[i] = C[s * E_NO + e] * expf(Esc[e]);
}

// ---------- 2. GEMM: syn[b][s][t] = sum_e S_e[b][t][e] * CT[e][s] ----------
__global__ void __launch_bounds__(128) gemm_kernel(const float* __restrict__ S_e) {
    __shared__ float sS[256 * 33];      // 256 rows x 32 e, padded
    __shared__ float sC[32 * 20];       // [e_loc][s]
    const int b = blockIdx.y;
    const int t0 = blockIdx.x * 256;
    const int tid = threadIdx.x;

    unsigned long long acc0[10], acc1[10];
#pragma unroll
    for (int s = 0; s < 10; s++) { acc0[s] = 0ull; acc1[s] = 0ull; }

    const float* Sb = S_e + (size_t)b * T_DATA * E_NO;

    for (int e0 = 0; e0 < E_NO; e0 += 32) {
#pragma unroll
        for (int k = 0; k < 5; k++) {
            int i = tid + k * 128;
            sC[i] = g_CT[(e0 + i / 20) * 20 + (i % 20)];
        }
#pragma unroll 8
        for (int k = 0; k < 64; k++) {
            int l = tid + k * 128;
            int r = l >> 5, j = l & 31;
            int t = t0 + r;
            sS[r * 33 + j] = (t < T_DATA) ? Sb[(size_t)t * E_NO + e0 + j] : 0.0f;
        }
        __syncthreads();
#pragma unroll 8
        for (int j = 0; j < 32; j++) {
            unsigned long long cp[10];
#pragma unroll
            for (int s = 0; s < 10; s++)
                cp[s] = *(const unsigned long long*)&sC[j * 20 + 2 * s];
            float v0 = sS[tid * 33 + j];
            float v1 = sS[(tid + 128) * 33 + j];
            unsigned long long v0p = pk2(v0, v0), v1p = pk2(v1, v1);
#pragma unroll
            for (int s = 0; s < 10; s++) {
                acc0[s] = ffma2(v0p, cp[s], acc0[s]);
                acc1[s] = ffma2(v1p, cp[s], acc1[s]);
            }
        }
        __syncthreads();
    }

    int ta = t0 + tid;
    if (ta < T_DATA) {
#pragma unroll
        for (int s = 0; s < 10; s++) {
            float2 f = upk2(acc0[s]);
            g_syn[((size_t)b * SUB_NO + 2 * s)     * T_DATA + ta] = f.x;
            g_syn[((size_t)b * SUB_NO + 2 * s + 1) * T_DATA + ta] = f.y;
        }
    }
    int tb = t0 + 128 + tid;
    if (tb < T_DATA) {
#pragma unroll
        for (int s = 0; s < 10; s++) {
            float2 f = upk2(acc1[s]);
            g_syn[((size_t)b * SUB_NO + 2 * s)     * T_DATA + tb] = f.x;
            g_syn[((size_t)b * SUB_NO + 2 * s + 1) * T_DATA + tb] = f.y;
        }
    }
}

// ---------- 3. depthwise causal conv ----------
__global__ void __launch_bounds__(256) conv_kernel(const float* __restrict__ W1) {
    const int bs = blockIdx.x;            // 0..159
    const int b = bs / SUB_NO, s = bs % SUB_NO;
    __shared__ float ss[T_NO - 1 + T_DATA];   // 49 zeros + 5000
    const int tid = threadIdx.x;

    for (int i = tid; i < T_NO - 1; i += 256) ss[i] = 0.0f;
    const float* sp = g_syn + ((size_t)b * SUB_NO + s) * T_DATA;
    for (int i = tid; i < T_DATA; i += 256) ss[T_NO - 1 + i] = sp[i];
    __syncthreads();

    for (int h = 0; h < HID_NO; h++) {
        const int c = s * HID_NO + h;
        float w[T_NO];
#pragma unroll
        for (int i = 0; i < T_NO; i++) w[i] = __ldg(&W1[c * T_NO + i]);
        float* cp = g_conv + ((size_t)(b * SH_NO + c)) * T_DATA;
        for (int t = tid; t < T_DATA; t += 256) {
            float acc = 0.0f;
#pragma unroll
            for (int tau = 0; tau < T_NO; tau++)
                acc = fmaf(ss[T_NO - 1 + t - tau], w[tau], acc);
            cp[t] = acc;
        }
    }
}

// ---------- 4. recurrence: 3-warp specialized pipeline ----------
// y[t] = tanh( sum_{tau=1..50} y[t-tau]*Wh[c][tau-1] + conv[b][c][t] + b1[c] )
// Warp A (0): serial chain, taps 1..20, f32x2 paired scatter window.
// Warp B1 (1): taps 21..35 + conv + bias for chunk k+1; conv prefetch.
// Warp B2 (2): taps 36..50 for chunk k+1; output stores (ew2*y).
__global__ void __launch_bounds__(96, 1) recur_kernel(const float* __restrict__ Wh,
                                                      const float* __restrict__ b1,
                                                      const float* __restrict__ W2) {
    // rows of 6 ull = 48B; all 64-bit accesses 8B aligned
    __shared__ unsigned long long s_y[2][32][6];
    __shared__ unsigned long long s_p1[2][32][6];
    __shared__ unsigned long long s_p2[2][32][6];

    const int lane = threadIdx.x & 31;
    const int warp = threadIdx.x >> 5;
    const int ch = blockIdx.x * 32 + lane;        // 0..1599
    const int c = ch % SH_NO;

    if (warp == 0) {
        // ---------------- Warp A ----------------
        float w[TA + 1];
#pragma unroll
        for (int i = 0; i < TA; i++) w[i] = __ldg(&Wh[c * T_NO + i]);  // tau = i+1
        w[TA] = 0.0f;
        unsigned long long wp0[10], wp1[10];
#pragma unroll
        for (int i = 0; i < 10; i++) {
            wp0[i] = pk2(w[2 * i], w[2 * i + 1]);
            wp1[i] = pk2(w[2 * i + 1], w[2 * i + 2]);
        }

        unsigned long long A2[15];   // acc slots 0..29, pair m = (acc[2m], acc[2m+1])
#pragma unroll
        for (int m = 0; m < 15; m++) A2[m] = 0ull;

        __syncthreads();             // matches helper prologue

        for (int k = 0; k < NCHUNKS; k++) {
            const unsigned long long* pp1 = &s_p1[k & 1][lane][0];
            const unsigned long long* pp2 = &s_p2[k & 1][lane][0];
#pragma unroll
            for (int m = 0; m < 5; m++)
                A2[m] = add2(A2[m], add2(pp1[m], pp2[m]));

            unsigned long long* yrow = &s_y[k & 1][lane][0];
#pragma unroll
            for (int pp = 0; pp < 5; pp++) {       // steps p=2*pp, p+1
                float2 a = upk2(A2[pp]);
                float y0 = tanh_fast(a.x);
                float v1 = fmaf(y0, w[0], a.y);    // tap-1 bridge
                float y1 = tanh_fast(v1);
                yrow[pp] = pk2(y0, y1);
                unsigned long long yy0 = pk2(y0, y0);
                unsigned long long yy1 = pk2(y1, y1);
#pragma unroll
                for (int i = 0; i < 10; i++)
                    A2[pp + 1 + i] = ffma2(yy0, wp1[i],
                                     ffma2(yy1, wp0[i], A2[pp + 1 + i]));
            }
            // shift window by PCH=10 (5 pairs)
#pragma unroll
            for (int m = 0; m < 10; m++) A2[m] = A2[m + 5];
#pragma unroll
            for (int m = 10; m < 15; m++) A2[m] = 0ull;
            __syncthreads();
        }
    } else if (warp == 1) {
        // ---------------- Warp B1: taps 21..35 + conv + bias ----------------
        float w[TBH];
#pragma unroll
        for (int u = 0; u < TBH; u++) w[u] = __ldg(&Wh[c * T_NO + TA + u]);
        const float bias = b1[c];
        const float* cv = g_conv + (size_t)ch * T_DATA;

        float yw[25];                 // yw[i] = y[k*10 - 25 + i]
#pragma unroll
        for (int i = 0; i < 25; i++) yw[i] = 0.0f;

        float cn[10];                 // conv of chunk k+1
        {   // prologue: part for chunk 0 + preload chunk 1
            float cb[10];
#pragma unroll
            for (int j = 0; j < 10; j += 2) {
                float2 t = *(const float2*)(cv + j);
                cb[j] = t.x; cb[j + 1] = t.y;
            }
            float* pr = (float*)&s_p1[0][lane][0];
#pragma unroll
            for (int j = 0; j < 10; j++) pr[j] = cb[j] + bias;
#pragma unroll
            for (int j = 0; j < 10; j += 2) {
                float2 t = *(const float2*)(cv + 10 + j);
                cn[j] = t.x; cn[j + 1] = t.y;
            }
        }
        __syncthreads();

        for (int k = 0; k < NCHUNKS; k++) {
            float cf[10];
            if (k + 2 < NCHUNKS) {    // prefetch conv chunk k+2
#pragma unroll
                for (int j = 0; j < 10; j += 2) {
                    float2 t = *(const float2*)(cv + (k + 2) * PCH + j);
                    cf[j] = t.x; cf[j + 1] = t.y;
                }
            }
            if (k > 0) {              // absorb ys of chunk k-1
                const unsigned long long* yr = &s_y[(k - 1) & 1][lane][0];
                float yn[10];
#pragma unroll
                for (int q = 0; q < 5; q++) {
                    float2 t = upk2(yr[q]);
                    yn[2 * q] = t.x; yn[2 * q + 1] = t.y;
                }
#pragma unroll
                for (int i = 0; i < 15; i++) yw[i] = yw[i + 10];
#pragma unroll
                for (int j = 0; j < 10; j++) yw[15 + j] = yn[j];
            }
            if (k + 1 < NCHUNKS) {    // part for chunk k+1
                float part[10];
#pragma unroll
                for (int j = 0; j < 10; j++) part[j] = cn[j] + bias;
#pragma unroll
                for (int j = 0; j < 10; j++)
#pragma unroll
                    for (int u = 0; u < TBH; u++)
                        part[j] = fmaf(yw[14 + j - u], w[u], part[j]);
                float* pw = (float*)&s_p1[(k + 1) & 1][lane][0];
#pragma unroll
                for (int j = 0; j < 10; j++) pw[j] = part[j];
            }
            if (k + 2 < NCHUNKS) {
#pragma unroll
                for (int j = 0; j < 10; j++) cn[j] = cf[j];
            }
            __syncthreads();
        }
    } else {
        // ---------------- Warp B2: taps 36..50 + output stores ----------------
        float w[TBH];
#pragma unroll
        for (int u = 0; u < TBH; u++) w[u] = __ldg(&Wh[c * T_NO + TA + TBH + u]);
        const float ew2 = expf(W2[c]);
        float* yo = g_ybuf + (size_t)ch * T_DATA;

        float yw[40];                 // yw[i] = y[k*10 - 40 + i]
#pragma unroll
        for (int i = 0; i < 40; i++) yw[i] = 0.0f;

        {   // prologue: part2 for chunk 0 = 0
            float* pr = (float*)&s_p2[0][lane][0];
#pragma unroll
            for (int j = 0; j < 10; j++) pr[j] = 0.0f;
        }
        __syncthreads();

        for (int k = 0; k < NCHUNKS; k++) {
            if (k > 0) {
                const unsigned long long* yr = &s_y[(k - 1) & 1][lane][0];
                float yn[10];
#pragma unroll
                for (int q = 0; q < 5; q++) {
                    float2 t = upk2(yr[q]);
                    yn[2 * q] = t.x; yn[2 * q + 1] = t.y;
                }
                float* yob = yo + (size_t)(k - 1) * PCH;
#pragma unroll
                for (int q = 0; q < 5; q++)
                    *(float2*)(yob + 2 * q) =
                        make_float2(ew2 * yn[2 * q], ew2 * yn[2 * q + 1]);
#pragma unroll
                for (int i = 0; i < 30; i++) yw[i] = yw[i + 10];
#pragma unroll
                for (int j = 0; j < 10; j++) yw[30 + j] = yn[j];
            }
            if (k + 1 < NCHUNKS) {
                float part[10];
#pragma unroll
                for (int j = 0; j < 10; j++) part[j] = 0.0f;
#pragma unroll
                for (int j = 0; j < 10; j++)
#pragma unroll
                    for (int u = 0; u < TBH; u++)
                        part[j] = fmaf(yw[14 + j - u], w[u], part[j]);
                float* pw = (float*)&s_p2[(k + 1) & 1][lane][0];
#pragma unroll
                for (int j = 0; j < 10; j++) pw[j] = part[j];
            }
            __syncthreads();
        }
        {   // epilogue: outputs of final chunk
            const unsigned long long* yr = &s_y[(NCHUNKS - 1) & 1][lane][0];
            float* yob = yo + (size_t)(NCHUNKS - 1) * PCH;
#pragma unroll
            for (int q = 0; q < 5; q++) {
                float2 t = upk2(yr[q]);
                *(float2*)(yob + 2 * q) = make_float2(ew2 * t.x, ew2 * t.y);
            }
        }
    }
}

// ---------- 5. reduce: out[b][t] = V_o + sum_c ybuf[b][c][t] ----------
__global__ void __launch_bounds__(256) reduce_kernel(const float* __restrict__ V_o,
                                                     float* __restrict__ out) {
    int idx = blockIdx.x * 256 + threadIdx.x;
    if (idx >= B_NO * T_DATA) return;
    int b = idx / T_DATA, t = idx % T_DATA;
    const float* p = g_ybuf + (size_t)b * SH_NO * T_DATA + t;
    float a = V_o[0];
#pragma unroll 10
    for (int c = 0; c < SH_NO; c++) a += p[(size_t)c * T_DATA];
    out[idx] = a;
}

extern "C" void kernel_launch(void* const* d_in, const int* in_sizes, int n_in,
                              void* d_out, int out_size) {
    const float* S_e     = (const float*)d_in[0];
    // d_in[1] S_i, d_in[3] C_syn_i, d_in[5] I_scale, d_in[10] W_sub: unused
    const float* C_syn_e = (const float*)d_in[2];
    const float* E_scale = (const float*)d_in[4];
    const float* W1      = (const float*)d_in[6];
    const float* W2      = (const float*)d_in[7];
    const float* b1      = (const float*)d_in[8];
    const float* Wh      = (const float*)d_in[9];
    const float* V_o     = (const float*)d_in[11];
    float* out = (float*)d_out;

    prep_kernel<<<(E_NO * SUB_NO + 255) / 256, 256>>>(C_syn_e, E_scale);
    dim3 gg((T_DATA + 255) / 256, B_NO);
    gemm_kernel<<<gg, 128>>>(S_e);
    conv_kernel<<<B_NO * SUB_NO, 256>>>(W1);
    recur_kernel<<<(NCH + 31) / 32, 96>>>(Wh, b1, W2);
    reduce_kernel<<<(B_NO * T_DATA + 255) / 256, 256>>>(V_o, out);
}

// round 4
// speedup vs baseline: 1.3206x; 1.0009x over previous
#include <cuda_runtime.h>
#include <cuda_bf16.h>
#include <cstdint>

// Problem dims
#define B_NO   8
#define T_DATA 5000
#define E_NO   2000
#define SUB_NO 20
#define HID_NO 10
#define SH_NO  (SUB_NO * HID_NO)   // 200
#define T_NO   50
#define NCH    (B_NO * SH_NO)      // 1600 channels

// Recurrence pipeline config
#define PCH 10
#define NCHUNKS (T_DATA / PCH)     // 500
#define TA  20                     // warp A taps 1..20 (minimum for PCH=10)
#define TBH 15                     // taps per helper warp (21..35 and 36..50)

// Scratch (device globals — no allocation at runtime)
__device__ float g_CT[E_NO * SUB_NO];                   // [e][s] scaled C
__device__ float g_syn[B_NO * SUB_NO * T_DATA];         // [b][s][t]
__device__ float g_conv[B_NO * SH_NO * (size_t)T_DATA]; // [b][c][t]
__device__ float g_ybuf[B_NO * SH_NO * (size_t)T_DATA]; // [b][c][t]  ew2*y

// ---------- f32x2 helpers ----------
__device__ __forceinline__ unsigned long long pk2(float x, float y) {
    unsigned long long r;
    asm("mov.b64 %0, {%1, %2};" : "=l"(r) : "f"(x), "f"(y));
    return r;
}
__device__ __forceinline__ unsigned long long ffma2(unsigned long long a,
                                                    unsigned long long b,
                                                    unsigned long long c) {
    unsigned long long d;
    asm("fma.rn.f32x2 %0, %1, %2, %3;" : "=l"(d) : "l"(a), "l"(b), "l"(c));
    return d;
}
__device__ __forceinline__ unsigned long long add2(unsigned long long a,
                                                   unsigned long long b) {
    unsigned long long d;
    asm("add.rn.f32x2 %0, %1, %2;" : "=l"(d) : "l"(a), "l"(b));
    return d;
}
__device__ __forceinline__ float2 upk2(unsigned long long v) {
    float2 f;
    asm("mov.b64 {%0, %1}, %2;" : "=f"(f.x), "=f"(f.y) : "l"(v));
    return f;
}

__device__ __forceinline__ float tanh_fast(float x) {
    // tanh(x) = 1 - 2/(e^{2x}+1); inf-safe; chain: FMUL+EX2+FADD+RCP+FFMA
    float z = x * 2.8853900817779268f;   // 2*log2(e)
    float e;
    asm("ex2.approx.f32 %0, %1;" : "=f"(e) : "f"(z));
    float r;
    asm("rcp.approx.f32 %0, %1;" : "=f"(r) : "f"(e + 1.0f));
    return fmaf(-2.0f, r, 1.0f);
}

// ---------- 1. prep: CT[e][s] = C[s][e] * exp(E_scale[e]) ----------
__global__ void prep_kernel(const float* __restrict__ C, const float* __restrict__ Esc) {
    int i = blockIdx.x * 256 + threadIdx.x;
    if (i >= E_NO * SUB_NO) return;
    int e = i / SUB_NO, s = i % SUB_NO;
    g_CT[i] = C[s * E_NO + e] * expf(Esc[e]);
}

// ---------- 2. GEMM: syn[b][s][t] = sum_e S_e[b][t][e] * CT[e][s] ----------
__global__ void __launch_bounds__(128) gemm_kernel(const float* __restrict__ S_e) {
    __shared__ float sS[256 * 33];      // 256 rows x 32 e, padded
    __shared__ float sC[32 * 20];       // [e_loc][s]
    const int b = blockIdx.y;
    const int t0 = blockIdx.x * 256;
    const int tid = threadIdx.x;

    unsigned long long acc0[10], acc1[10];
#pragma unroll
    for (int s = 0; s < 10; s++) { acc0[s] = 0ull; acc1[s] = 0ull; }

    const float* Sb = S_e + (size_t)b * T_DATA * E_NO;

    for (int e0 = 0; e0 < E_NO; e0 += 32) {
#pragma unroll
        for (int k = 0; k < 5; k++) {
            int i = tid + k * 128;
            sC[i] = g_CT[(e0 + i / 20) * 20 + (i % 20)];
        }
#pragma unroll 8
        for (int k = 0; k < 64; k++) {
            int l = tid + k * 128;
            int r = l >> 5, j = l & 31;
            int t = t0 + r;
            sS[r * 33 + j] = (t < T_DATA) ? Sb[(size_t)t * E_NO + e0 + j] : 0.0f;
        }
        __syncthreads();
#pragma unroll 8
        for (int j = 0; j < 32; j++) {
            unsigned long long cp[10];
#pragma unroll
            for (int s = 0; s < 10; s++)
                cp[s] = *(const unsigned long long*)&sC[j * 20 + 2 * s];
            float v0 = sS[tid * 33 + j];
            float v1 = sS[(tid + 128) * 33 + j];
            unsigned long long v0p = pk2(v0, v0), v1p = pk2(v1, v1);
#pragma unroll
            for (int s = 0; s < 10; s++) {
                acc0[s] = ffma2(v0p, cp[s], acc0[s]);
                acc1[s] = ffma2(v1p, cp[s], acc1[s]);
            }
        }
        __syncthreads();
    }

    int ta = t0 + tid;
    if (ta < T_DATA) {
#pragma unroll
        for (int s = 0; s < 10; s++) {
            float2 f = upk2(acc0[s]);
            g_syn[((size_t)b * SUB_NO + 2 * s)     * T_DATA + ta] = f.x;
            g_syn[((size_t)b * SUB_NO + 2 * s + 1) * T_DATA + ta] = f.y;
        }
    }
    int tb = t0 + 128 + tid;
    if (tb < T_DATA) {
#pragma unroll
        for (int s = 0; s < 10; s++) {
            float2 f = upk2(acc1[s]);
            g_syn[((size_t)b * SUB_NO + 2 * s)     * T_DATA + tb] = f.x;
            g_syn[((size_t)b * SUB_NO + 2 * s + 1) * T_DATA + tb] = f.y;
        }
    }
}

// ---------- 3. depthwise causal conv ----------
__global__ void __launch_bounds__(256) conv_kernel(const float* __restrict__ W1) {
    const int bs = blockIdx.x;            // 0..159
    const int b = bs / SUB_NO, s = bs % SUB_NO;
    __shared__ float ss[T_NO - 1 + T_DATA];   // 49 zeros + 5000
    const int tid = threadIdx.x;

    for (int i = tid; i < T_NO - 1; i += 256) ss[i] = 0.0f;
    const float* sp = g_syn + ((size_t)b * SUB_NO + s) * T_DATA;
    for (int i = tid; i < T_DATA; i += 256) ss[T_NO - 1 + i] = sp[i];
    __syncthreads();

    for (int h = 0; h < HID_NO; h++) {
        const int c = s * HID_NO + h;
        float w[T_NO];
#pragma unroll
        for (int i = 0; i < T_NO; i++) w[i] = __ldg(&W1[c * T_NO + i]);
        float* cp = g_conv + ((size_t)(b * SH_NO + c)) * T_DATA;
        for (int t = tid; t < T_DATA; t += 256) {
            float acc = 0.0f;
#pragma unroll
            for (int tau = 0; tau < T_NO; tau++)
                acc = fmaf(ss[T_NO - 1 + t - tau], w[tau], acc);
            cp[t] = acc;
        }
    }
}

// ---------- 4. recurrence: 3-warp specialized pipeline ----------
// y[t] = tanh( sum_{tau=1..50} y[t-tau]*Wh[c][tau-1] + conv[b][c][t] + b1[c] )
// Warp A (0): serial chain, taps 1..20, f32x2 paired scatter window.
// Warp B1 (1): taps 21..35 + conv + bias for chunk k+1; conv prefetch.
// Warp B2 (2): taps 36..50 for chunk k+1; output stores (ew2*y).
__global__ void __launch_bounds__(96, 1) recur_kernel(const float* __restrict__ Wh,
                                                      const float* __restrict__ b1,
                                                      const float* __restrict__ W2) {
    // rows of 6 ull = 48B; all 64-bit accesses 8B aligned
    __shared__ unsigned long long s_y[2][32][6];
    __shared__ unsigned long long s_p1[2][32][6];
    __shared__ unsigned long long s_p2[2][32][6];

    const int lane = threadIdx.x & 31;
    const int warp = threadIdx.x >> 5;
    const int ch = blockIdx.x * 32 + lane;        // 0..1599
    const int c = ch % SH_NO;

    if (warp == 0) {
        // ---------------- Warp A ----------------
        float w[TA + 1];
#pragma unroll
        for (int i = 0; i < TA; i++) w[i] = __ldg(&Wh[c * T_NO + i]);  // tau = i+1
        w[TA] = 0.0f;
        unsigned long long wp0[10], wp1[10];
#pragma unroll
        for (int i = 0; i < 10; i++) {
            wp0[i] = pk2(w[2 * i], w[2 * i + 1]);
            wp1[i] = pk2(w[2 * i + 1], w[2 * i + 2]);
        }

        unsigned long long A2[15];   // acc slots 0..29, pair m = (acc[2m], acc[2m+1])
#pragma unroll
        for (int m = 0; m < 15; m++) A2[m] = 0ull;

        __syncthreads();             // matches helper prologue

        for (int k = 0; k < NCHUNKS; k++) {
            const unsigned long long* pp1 = &s_p1[k & 1][lane][0];
            const unsigned long long* pp2 = &s_p2[k & 1][lane][0];
#pragma unroll
            for (int m = 0; m < 5; m++)
                A2[m] = add2(A2[m], add2(pp1[m], pp2[m]));

            unsigned long long* yrow = &s_y[k & 1][lane][0];
#pragma unroll
            for (int pp = 0; pp < 5; pp++) {       // steps p=2*pp, p+1
                float2 a = upk2(A2[pp]);
                float y0 = tanh_fast(a.x);
                float v1 = fmaf(y0, w[0], a.y);    // tap-1 bridge
                float y1 = tanh_fast(v1);
                yrow[pp] = pk2(y0, y1);
                unsigned long long yy0 = pk2(y0, y0);
                unsigned long long yy1 = pk2(y1, y1);
#pragma unroll
                for (int i = 0; i < 10; i++)
                    A2[pp + 1 + i] = ffma2(yy0, wp1[i],
                                     ffma2(yy1, wp0[i], A2[pp + 1 + i]));
            }
            // shift window by PCH=10 (5 pairs)
#pragma unroll
            for (int m = 0; m < 10; m++) A2[m] = A2[m + 5];
#pragma unroll
            for (int m = 10; m < 15; m++) A2[m] = 0ull;
            __syncthreads();
        }
    } else if (warp == 1) {
        // ---------------- Warp B1: taps 21..35 + conv + bias ----------------
        float w[TBH];
#pragma unroll
        for (int u = 0; u < TBH; u++) w[u] = __ldg(&Wh[c * T_NO + TA + u]);
        const float bias = b1[c];
        const float* cv = g_conv + (size_t)ch * T_DATA;

        float yw[25];                 // yw[i] = y[k*10 - 25 + i]
#pragma unroll
        for (int i = 0; i < 25; i++) yw[i] = 0.0f;

        float cn[10];                 // conv of chunk k+1
        {   // prologue: part for chunk 0 + preload chunk 1
            float cb[10];
#pragma unroll
            for (int j = 0; j < 10; j += 2) {
                float2 t = *(const float2*)(cv + j);
                cb[j] = t.x; cb[j + 1] = t.y;
            }
            float* pr = (float*)&s_p1[0][lane][0];
#pragma unroll
            for (int j = 0; j < 10; j++) pr[j] = cb[j] + bias;
#pragma unroll
            for (int j = 0; j < 10; j += 2) {
                float2 t = *(const float2*)(cv + 10 + j);
                cn[j] = t.x; cn[j + 1] = t.y;
            }
        }
        __syncthreads();

        for (int k = 0; k < NCHUNKS; k++) {
            float cf[10];
            if (k + 2 < NCHUNKS) {    // prefetch conv chunk k+2
#pragma unroll
                for (int j = 0; j < 10; j += 2) {
                    float2 t = *(const float2*)(cv + (k + 2) * PCH + j);
                    cf[j] = t.x; cf[j + 1] = t.y;
                }
            }
            if (k > 0) {              // absorb ys of chunk k-1
                const unsigned long long* yr = &s_y[(k - 1) & 1][lane][0];
                float yn[10];
#pragma unroll
                for (int q = 0; q < 5; q++) {
                    float2 t = upk2(yr[q]);
                    yn[2 * q] = t.x; yn[2 * q + 1] = t.y;
                }
#pragma unroll
                for (int i = 0; i < 15; i++) yw[i] = yw[i + 10];
#pragma unroll
                for (int j = 0; j < 10; j++) yw[15 + j] = yn[j];
            }
            if (k + 1 < NCHUNKS) {    // part for chunk k+1
                float part[10];
#pragma unroll
                for (int j = 0; j < 10; j++) part[j] = cn[j] + bias;
#pragma unroll
                for (int j = 0; j < 10; j++)
#pragma unroll
                    for (int u = 0; u < TBH; u++)
                        part[j] = fmaf(yw[14 + j - u], w[u], part[j]);
                float* pw = (float*)&s_p1[(k + 1) & 1][lane][0];
#pragma unroll
                for (int j = 0; j < 10; j++) pw[j] = part[j];
            }
            if (k + 2 < NCHUNKS) {
#pragma unroll
                for (int j = 0; j < 10; j++) cn[j] = cf[j];
            }
            __syncthreads();
        }
    } else {
        // ---------------- Warp B2: taps 36..50 + output stores ----------------
        float w[TBH];
#pragma unroll
        for (int u = 0; u < TBH; u++) w[u] = __ldg(&Wh[c * T_NO + TA + TBH + u]);
        const float ew2 = expf(W2[c]);
        float* yo = g_ybuf + (size_t)ch * T_DATA;

        float yw[40];                 // yw[i] = y[k*10 - 40 + i]
#pragma unroll
        for (int i = 0; i < 40; i++) yw[i] = 0.0f;

        {   // prologue: part2 for chunk 0 = 0
            float* pr = (float*)&s_p2[0][lane][0];
#pragma unroll
            for (int j = 0; j < 10; j++) pr[j] = 0.0f;
        }
        __syncthreads();

        for (int k = 0; k < NCHUNKS; k++) {
            if (k > 0) {
                const unsigned long long* yr = &s_y[(k - 1) & 1][lane][0];
                float yn[10];
#pragma unroll
                for (int q = 0; q < 5; q++) {
                    float2 t = upk2(yr[q]);
                    yn[2 * q] = t.x; yn[2 * q + 1] = t.y;
                }
                float* yob = yo + (size_t)(k - 1) * PCH;
#pragma unroll
                for (int q = 0; q < 5; q++)
                    *(float2*)(yob + 2 * q) =
                        make_float2(ew2 * yn[2 * q], ew2 * yn[2 * q + 1]);
#pragma unroll
                for (int i = 0; i < 30; i++) yw[i] = yw[i + 10];
#pragma unroll
                for (int j = 0; j < 10; j++) yw[30 + j] = yn[j];
            }
            if (k + 1 < NCHUNKS) {
                float part[10];
#pragma unroll
                for (int j = 0; j < 10; j++) part[j] = 0.0f;
#pragma unroll
                for (int j = 0; j < 10; j++)
#pragma unroll
                    for (int u = 0; u < TBH; u++)
                        part[j] = fmaf(yw[14 + j - u], w[u], part[j]);
                float* pw = (float*)&s_p2[(k + 1) & 1][lane][0];
#pragma unroll
                for (int j = 0; j < 10; j++) pw[j] = part[j];
            }
            __syncthreads();
        }
        {   // epilogue: outputs of final chunk
            const unsigned long long* yr = &s_y[(NCHUNKS - 1) & 1][lane][0];
            float* yob = yo + (size_t)(NCHUNKS - 1) * PCH;
#pragma unroll
            for (int q = 0; q < 5; q++) {
                float2 t = upk2(yr[q]);
                *(float2*)(yob + 2 * q) = make_float2(ew2 * t.x, ew2 * t.y);
            }
        }
    }
}

// ---------- 5. reduce: out[b][t] = V_o + sum_c ybuf[b][c][t] ----------
__global__ void __launch_bounds__(256) reduce_kernel(const float* __restrict__ V_o,
                                                     float* __restrict__ out) {
    int idx = blockIdx.x * 256 + threadIdx.x;
    if (idx >= B_NO * T_DATA) return;
    int b = idx / T_DATA, t = idx % T_DATA;
    const float* p = g_ybuf + (size_t)b * SH_NO * T_DATA + t;
    float a = V_o[0];
#pragma unroll 10
    for (int c = 0; c < SH_NO; c++) a += p[(size_t)c * T_DATA];
    out[idx] = a;
}

extern "C" void kernel_launch(void* const* d_in, const int* in_sizes, int n_in,
                              void* d_out, int out_size) {
    const float* S_e     = (const float*)d_in[0];
    // d_in[1] S_i, d_in[3] C_syn_i, d_in[5] I_scale, d_in[10] W_sub: unused
    const float* C_syn_e = (const float*)d_in[2];
    const float* E_scale = (const float*)d_in[4];
    const float* W1      = (const float*)d_in[6];
    const float* W2      = (const float*)d_in[7];
    const float* b1      = (const float*)d_in[8];
    const float* Wh      = (const float*)d_in[9];
    const float* V_o     = (const float*)d_in[11];
    float* out = (float*)d_out;

    prep_kernel<<<(E_NO * SUB_NO + 255) / 256, 256>>>(C_syn_e, E_scale);
    dim3 gg((T_DATA + 255) / 256, B_NO);
    gemm_kernel<<<gg, 128>>>(S_e);
    conv_kernel<<<B_NO * SUB_NO, 256>>>(W1);
    recur_kernel<<<(NCH + 31) / 32, 96>>>(Wh, b1, W2);
    reduce_kernel<<<(B_NO * T_DATA + 255) / 256, 256>>>(V_o, out);
}

// round 5
// speedup vs baseline: 2.2912x; 1.7350x over previous
#include <cuda_runtime.h>
#include <cstdint>

#define B_NO   8
#define T_DATA 5000
#define E_NO   2000
#define SUB_NO 20
#define HID_NO 10
#define SH_NO  200
#define T_NO   50
#define NCH    1600

#define PCH 10
#define NCHUNKS 500

__device__ float g_CT[E_NO * SUB_NO];
__device__ float g_syn[B_NO * SUB_NO * T_DATA];
__device__ float g_conv[B_NO * SH_NO * (size_t)T_DATA];
__device__ float g_ybuf[B_NO * SH_NO * (size_t)T_DATA];

__device__ __forceinline__ unsigned long long pk2(float x, float y) {
    unsigned long long r;
    asm("mov.b64 %0, {%1, %2};" : "=l"(r) : "f"(x), "f"(y));
    return r;
}
__device__ __forceinline__ unsigned long long ffma2(unsigned long long a,
                                                    unsigned long long b,
                                                    unsigned long long c) {
    unsigned long long d;
    asm("fma.rn.f32x2 %0, %1, %2, %3;" : "=l"(d) : "l"(a), "l"(b), "l"(c));
    return d;
}
__device__ __forceinline__ unsigned long long add2(unsigned long long a,
                                                   unsigned long long b) {
    unsigned long long d;
    asm("add.rn.f32x2 %0, %1, %2;" : "=l"(d) : "l"(a), "l"(b));
    return d;
}
__device__ __forceinline__ float2 upk2(unsigned long long v) {
    float2 f;
    asm("mov.b64 {%0, %1}, %2;" : "=f"(f.x), "=f"(f.y) : "l"(v));
    return f;
}
__device__ __forceinline__ float tanh_hw(float x) {
    float y;
    asm("tanh.approx.f32 %0, %1;" : "=f"(y) : "f"(x));
    return y;
}

// ---------- 1. prep ----------
__global__ void prep_kernel(const float* __restrict__ C, const float* __restrict__ Esc) {
    int i = blockIdx.x * 256 + threadIdx.x;
    if (i >= E_NO * SUB_NO) return;
    int e = i / SUB_NO, s = i % SUB_NO;
    g_CT[i] = C[s * E_NO + e] * expf(Esc[e]);
}

// ---------- 2. GEMM: syn[b][s][t] = sum_e S_e[b][t][e]*CT[e][s] ----------
// 64 thr, 128 t-rows/block (2/thread), e-tile 16, double-buffered smem.
#define ETILE 16
#define GROWS 128
#define GTHR  64
#define NTILE (E_NO / ETILE)

__global__ void __launch_bounds__(GTHR) gemm_kernel(const float* __restrict__ S_e) {
    __shared__ float sS[2][GROWS * 17];
    __shared__ float sC[2][ETILE * 20];
    const int b = blockIdx.y;
    const int t0 = blockIdx.x * GROWS;
    const int tid = threadIdx.x;
    const float* Sb = S_e + (size_t)b * T_DATA * E_NO;

    unsigned long long acc0[10], acc1[10];
#pragma unroll
    for (int s = 0; s < 10; s++) { acc0[s] = 0ull; acc1[s] = 0ull; }

    float4 pf[8];
    float pc[5];

#define LDG_TILE(E0)                                                        \
    {                                                                       \
        _Pragma("unroll")                                                   \
        for (int kk = 0; kk < 8; kk++) {                                    \
            int q = tid + kk * GTHR;                                        \
            int r = q >> 2, c4 = q & 3;                                     \
            int t = t0 + r;                                                 \
            pf[kk] = (t < T_DATA)                                           \
                ? *(const float4*)(Sb + (size_t)t * E_NO + (E0) + c4 * 4)   \
                : make_float4(0.f, 0.f, 0.f, 0.f);                          \
        }                                                                   \
        _Pragma("unroll")                                                   \
        for (int m = 0; m < 5; m++) pc[m] = g_CT[(E0) * 20 + tid * 5 + m];  \
    }

#define STS_TILE(BUF)                                                       \
    {                                                                       \
        _Pragma("unroll")                                                   \
        for (int kk = 0; kk < 8; kk++) {                                    \
            int q = tid + kk * GTHR;                                        \
            int r = q >> 2, c4 = q & 3;                                     \
            float* d = &sS[BUF][r * 17 + c4 * 4];                           \
            d[0] = pf[kk].x; d[1] = pf[kk].y;                               \
            d[2] = pf[kk].z; d[3] = pf[kk].w;                               \
        }                                                                   \
        _Pragma("unroll")                                                   \
        for (int m = 0; m < 5; m++) sC[BUF][tid * 5 + m] = pc[m];           \
    }

    LDG_TILE(0);
    STS_TILE(0);
    LDG_TILE(ETILE);
    __syncthreads();

    for (int it = 0; it < NTILE; it++) {
        const int cur = it & 1;
#pragma unroll
        for (int j = 0; j < ETILE; j++) {
            unsigned long long cp[10];
#pragma unroll
            for (int s = 0; s < 10; s++)
                cp[s] = *(const unsigned long long*)&sC[cur][j * 20 + 2 * s];
            float v0 = sS[cur][tid * 17 + j];
            float v1 = sS[cur][(tid + GTHR) * 17 + j];
            unsigned long long v0p = pk2(v0, v0), v1p = pk2(v1, v1);
#pragma unroll
            for (int s = 0; s < 10; s++) {
                acc0[s] = ffma2(v0p, cp[s], acc0[s]);
                acc1[s] = ffma2(v1p, cp[s], acc1[s]);
            }
        }
        if (it < NTILE - 1) {
            STS_TILE(cur ^ 1);
            if (it < NTILE - 2) LDG_TILE((it + 2) * ETILE);
            __syncthreads();
        }
    }

    int ta = t0 + tid;
    if (ta < T_DATA) {
#pragma unroll
        for (int s = 0; s < 10; s++) {
            float2 f = upk2(acc0[s]);
            g_syn[((size_t)b * SUB_NO + 2 * s)     * T_DATA + ta] = f.x;
            g_syn[((size_t)b * SUB_NO + 2 * s + 1) * T_DATA + ta] = f.y;
        }
    }
    int tb = t0 + GTHR + tid;
    if (tb < T_DATA) {
#pragma unroll
        for (int s = 0; s < 10; s++) {
            float2 f = upk2(acc1[s]);
            g_syn[((size_t)b * SUB_NO + 2 * s)     * T_DATA + tb] = f.x;
            g_syn[((size_t)b * SUB_NO + 2 * s + 1) * T_DATA + tb] = f.y;
        }
    }
}

// ---------- 3. depthwise causal conv ----------
__global__ void __launch_bounds__(256) conv_kernel(const float* __restrict__ W1) {
    const int bs = blockIdx.x;
    const int b = bs / SUB_NO, s = bs % SUB_NO;
    __shared__ float ss[T_NO - 1 + T_DATA];
    const int tid = threadIdx.x;

    for (int i = tid; i < T_NO - 1; i += 256) ss[i] = 0.0f;
    const float* sp = g_syn + ((size_t)b * SUB_NO + s) * T_DATA;
    for (int i = tid; i < T_DATA; i += 256) ss[T_NO - 1 + i] = sp[i];
    __syncthreads();

    for (int h = 0; h < HID_NO; h++) {
        const int c = s * HID_NO + h;
        float w[T_NO];
#pragma unroll
        for (int i = 0; i < T_NO; i++) w[i] = __ldg(&W1[c * T_NO + i]);
        float* cp = g_conv + ((size_t)(b * SH_NO + c)) * T_DATA;
        for (int t = tid; t < T_DATA; t += 256) {
            float acc = 0.0f;
#pragma unroll
            for (int tau = 0; tau < T_NO; tau++)
                acc = fmaf(ss[T_NO - 1 + t - tau], w[tau], acc);
            cp[t] = acc;
        }
    }
}

// ---------- 4. recurrence: 4-warp pipeline ----------
// W0(A): taps 1..19 serial; W1: 20..29 + conv; W2: 30..39 + stores; W3: 40..50.
template<int TB0, int NT, int WD, int MODE>
__device__ __forceinline__ void run_helper(
    int lane, int ch, int c,
    const float* __restrict__ Wh, const float* __restrict__ b1,
    const float* __restrict__ W2l,
    unsigned long long (*s_y)[32][6], unsigned long long (*sp)[32][6])
{
    float w[NT];
#pragma unroll
    for (int u = 0; u < NT; u++) w[u] = __ldg(&Wh[c * T_NO + TB0 + u - 1]);
    const float bias = (MODE == 1) ? b1[c] : 0.0f;
    const float ew2  = (MODE == 2) ? expf(W2l[c]) : 0.0f;
    const float* cv = g_conv + (size_t)ch * T_DATA;
    float* yo = g_ybuf + (size_t)ch * T_DATA;

    float yw[WD];
#pragma unroll
    for (int i = 0; i < WD; i++) yw[i] = 0.0f;

    float cn[10];
    // prologue: partials for chunk 0
    if (MODE == 1) {
        float c0[10];
#pragma unroll
        for (int j = 0; j < 10; j += 2) {
            float2 t = *(const float2*)(cv + j);
            c0[j] = t.x; c0[j + 1] = t.y;
        }
        float* pr = (float*)&sp[0][lane][0];
#pragma unroll
        for (int j = 0; j < 10; j++) pr[j] = c0[j] + bias;
#pragma unroll
        for (int j = 0; j < 10; j += 2) {
            float2 t = *(const float2*)(cv + PCH + j);
            cn[j] = t.x; cn[j + 1] = t.y;
        }
    } else {
        float* pr = (float*)&sp[0][lane][0];
#pragma unroll
        for (int j = 0; j < 10; j++) pr[j] = 0.0f;
    }
    __syncthreads();                       // bar 0

    // peeled k=0: partials chunk 1 (zero history)
    {
        float* pr = (float*)&sp[1][lane][0];
        if (MODE == 1) {
#pragma unroll
            for (int j = 0; j < 10; j++) pr[j] = cn[j] + bias;
#pragma unroll
            for (int j = 0; j < 10; j += 2) {
                float2 t = *(const float2*)(cv + 2 * PCH + j);
                cn[j] = t.x; cn[j + 1] = t.y;
            }
        } else {
#pragma unroll
            for (int j = 0; j < 10; j++) pr[j] = 0.0f;
        }
    }
    __syncthreads();                       // bar 1

    for (int k = 1; k <= NCHUNKS - 2; k++) {
        float yn[10];
        {
            const unsigned long long* yr = &s_y[(k - 1) & 1][lane][0];
#pragma unroll
            for (int q = 0; q < 5; q++) {
                float2 t = upk2(yr[q]);
                yn[2 * q] = t.x; yn[2 * q + 1] = t.y;
            }
        }
        if (MODE == 2) {
            float* yob = yo + (size_t)(k - 1) * PCH;
#pragma unroll
            for (int q = 0; q < 5; q++)
                *(float2*)(yob + 2 * q) =
                    make_float2(ew2 * yn[2 * q], ew2 * yn[2 * q + 1]);
        }
#pragma unroll
        for (int i = 0; i < WD - 10; i++) yw[i] = yw[i + 10];
#pragma unroll
        for (int j = 0; j < 10; j++) yw[WD - 10 + j] = yn[j];

        float part[10];
        if (MODE == 1) {
#pragma unroll
            for (int j = 0; j < 10; j++) part[j] = cn[j] + bias;
            int nidx = (k + 2 <= NCHUNKS - 1) ? (k + 2) : (NCHUNKS - 1);
#pragma unroll
            for (int j = 0; j < 10; j += 2) {
                float2 t = *(const float2*)(cv + nidx * PCH + j);
                cn[j] = t.x; cn[j + 1] = t.y;
            }
        } else {
#pragma unroll
            for (int j = 0; j < 10; j++) part[j] = 0.0f;
        }
#pragma unroll
        for (int j = 0; j < 10; j++)
#pragma unroll
            for (int u = 0; u < NT; u++)
                part[j] = fmaf(yw[WD + 10 + j - TB0 - u], w[u], part[j]);

        float* pw = (float*)&sp[(k + 1) & 1][lane][0];
#pragma unroll
        for (int j = 0; j < 10; j++) pw[j] = part[j];
        __syncthreads();                   // bars 2..499
    }

    if (MODE == 2) {
        const unsigned long long* yr = &s_y[(NCHUNKS - 2) & 1][lane][0];
        float* yob = yo + (size_t)(NCHUNKS - 2) * PCH;
#pragma unroll
        for (int q = 0; q < 5; q++) {
            float2 t = upk2(yr[q]);
            *(float2*)(yob + 2 * q) = make_float2(ew2 * t.x, ew2 * t.y);
        }
    }
    __syncthreads();                       // bar 500
    if (MODE == 2) {
        const unsigned long long* yr = &s_y[(NCHUNKS - 1) & 1][lane][0];
        float* yob = yo + (size_t)(NCHUNKS - 1) * PCH;
#pragma unroll
        for (int q = 0; q < 5; q++) {
            float2 t = upk2(yr[q]);
            *(float2*)(yob + 2 * q) = make_float2(ew2 * t.x, ew2 * t.y);
        }
    }
}

__global__ void __launch_bounds__(128, 1) recur_kernel(const float* __restrict__ Wh,
                                                       const float* __restrict__ b1,
                                                       const float* __restrict__ W2l) {
    __shared__ unsigned long long s_y[2][32][6];
    __shared__ unsigned long long s_p1[2][32][6];
    __shared__ unsigned long long s_p2[2][32][6];
    __shared__ unsigned long long s_p3[2][32][6];

    const int lane = threadIdx.x & 31;
    const int warp = threadIdx.x >> 5;
    const int ch = blockIdx.x * 32 + lane;
    const int c = ch % SH_NO;

    if (warp == 0) {
        float w[21];
#pragma unroll
        for (int i = 0; i < 19; i++) w[i] = __ldg(&Wh[c * T_NO + i]);
        w[19] = 0.0f; w[20] = 0.0f;
        unsigned long long wp0[10], wp1[10];
#pragma unroll
        for (int i = 0; i < 10; i++) {
            wp0[i] = pk2(w[2 * i], w[2 * i + 1]);
            wp1[i] = pk2(w[2 * i + 1], w[2 * i + 2]);
        }

        unsigned long long A2[15];
#pragma unroll
        for (int m = 0; m < 15; m++) A2[m] = 0ull;

        __syncthreads();                   // bar 0

        for (int k = 0; k < NCHUNKS; k++) {
            const unsigned long long* pp1 = &s_p1[k & 1][lane][0];
            const unsigned long long* pp2 = &s_p2[k & 1][lane][0];
            const unsigned long long* pp3 = &s_p3[k & 1][lane][0];
#pragma unroll
            for (int m = 0; m < 5; m++)
                A2[m] = add2(A2[m], add2(add2(pp1[m], pp2[m]), pp3[m]));

            unsigned long long* yrow = &s_y[k & 1][lane][0];
#pragma unroll
            for (int pp = 0; pp < 5; pp++) {
                float2 a = upk2(A2[pp]);
                float y0 = tanh_hw(a.x);
                float v1 = fmaf(y0, w[0], a.y);
                float y1 = tanh_hw(v1);
                yrow[pp] = pk2(y0, y1);
                unsigned long long yy0 = pk2(y0, y0);
                unsigned long long yy1 = pk2(y1, y1);
#pragma unroll
                for (int i = 0; i < 10; i++)
                    A2[pp + 1 + i] = ffma2(yy0, wp1[i],
                                     ffma2(yy1, wp0[i], A2[pp + 1 + i]));
            }
#pragma unroll
            for (int m = 0; m < 10; m++) A2[m] = A2[m + 5];
#pragma unroll
            for (int m = 10; m < 15; m++) A2[m] = 0ull;
            __syncthreads();               // bars 1..500
        }
    } else if (warp == 1) {
        run_helper<20, 10, 19, 1>(lane, ch, c, Wh, b1, W2l, s_y, s_p1);
    } else if (warp == 2) {
        run_helper<30, 10, 29, 2>(lane, ch, c, Wh, b1, W2l, s_y, s_p2);
    } else {
        run_helper<40, 11, 40, 0>(lane, ch, c, Wh, b1, W2l, s_y, s_p3);
    }
}

// ---------- 5. reduce ----------
__global__ void __launch_bounds__(256) reduce_kernel(const float* __restrict__ V_o,
                                                     float* __restrict__ out) {
    int idx = blockIdx.x * 256 + threadIdx.x;
    if (idx >= B_NO * T_DATA) return;
    int b = idx / T_DATA, t = idx % T_DATA;
    const float* p = g_ybuf + (size_t)b * SH_NO * T_DATA + t;
    float a = V_o[0];
#pragma unroll 10
    for (int c = 0; c < SH_NO; c++) a += p[(size_t)c * T_DATA];
    out[idx] = a;
}

extern "C" void kernel_launch(void* const* d_in, const int* in_sizes, int n_in,
                              void* d_out, int out_size) {
    const float* S_e     = (const float*)d_in[0];
    const float* C_syn_e = (const float*)d_in[2];
    const float* E_scale = (const float*)d_in[4];
    const float* W1      = (const float*)d_in[6];
    const float* W2      = (const float*)d_in[7];
    const float* b1      = (const float*)d_in[8];
    const float* Wh      = (const float*)d_in[9];
    const float* V_o     = (const float*)d_in[11];
    float* out = (float*)d_out;

    prep_kernel<<<(E_NO * SUB_NO + 255) / 256, 256>>>(C_syn_e, E_scale);
    dim3 gg((T_DATA + GROWS - 1) / GROWS, B_NO);
    gemm_kernel<<<gg, GTHR>>>(S_e);
    conv_kernel<<<B_NO * SUB_NO, 256>>>(W1);
    recur_kernel<<<NCH / 32, 128>>>(Wh, b1, W2);
    reduce_kernel<<<(B_NO * T_DATA + 255) / 256, 256>>>(V_o, out);
}